// round 6
// baseline (speedup 1.0000x reference)
#include <cuda_runtime.h>
#include <cuda_bf16.h>
#include <cstdint>

// ============================================================================
// Problem constants
//   out[b, f*32+e] = sum_h relu(x[b,f]*w1[f,h]+b1[f,h]) * w2[f,h,e] + b2[f,e]
// ============================================================================
#define B_TOT 16384
#define F_TOT 128
#define H_DIM 128
#define E_DIM 32

static constexpr int M_TILE   = 128;                  // rows per tile (4 warps x 32)
static constexpr int M_ITERS  = 8;                    // tiles per CTA
static constexpr int MGRPS    = (B_TOT / M_TILE) / M_ITERS;  // 16
static constexpr int GRID     = F_TOT * MGRPS;        // 2048
static constexpr int STR      = 136;                  // halves per w2^T row (pad 8 -> conflict-free)

// mma.sync m16n8k16 bf16 (baseline PTX — valid on plain sm_103 target)
#define MMA16816(C, a0, a1, a2, a3, b0, b1) \
    asm volatile( \
        "mma.sync.aligned.m16n8k16.row.col.f32.bf16.bf16.f32 " \
        "{%0,%1,%2,%3}, {%4,%5,%6,%7}, {%8,%9}, {%0,%1,%2,%3};" \
        : "+f"((C)[0]), "+f"((C)[1]), "+f"((C)[2]), "+f"((C)[3]) \
        : "r"(a0), "r"(a1), "r"(a2), "r"(a3), "r"(b0), "r"(b1))

// pack {lo=a, hi=b} as bf16x2 (round-to-nearest)
#define PACK_BF16X2(result, a, b) \
    asm("cvt.rn.bf16x2.f32 %0, %1, %2;" : "=r"(result) : "f"(b), "f"(a))

__global__ void __launch_bounds__(128)
dense_feat_emb_kernel(const float* __restrict__ x,
                      const float* __restrict__ w1,
                      const float* __restrict__ b1,
                      const float* __restrict__ w2,
                      const float* __restrict__ b2,
                      float* __restrict__ out)
{
    __shared__ float2 pw[H_DIM];                    // {w1, b1} per hidden unit
    __shared__ float  b2s[E_DIM];
    __shared__ unsigned short w2hi[E_DIM * STR];    // w2^T hi (truncated bf16)
    __shared__ unsigned short w2lo[E_DIM * STR];    // w2^T lo (bf16-RN of residual)

    const int tid  = threadIdx.x;
    const int lane = tid & 31;
    const int warp = tid >> 5;
    const int grp  = lane >> 2;   // 0..7
    const int tig  = lane & 3;    // 0..3

    const int f    = blockIdx.x & (F_TOT - 1);
    const int mgrp = blockIdx.x >> 7;

    // ---- per-feature params -> smem ----
    pw[tid] = make_float2(w1[f * H_DIM + tid], b1[f * H_DIM + tid]);
    if (tid < E_DIM) b2s[tid] = b2[f * E_DIM + tid];

    // ---- w2[f] (H x E row-major) -> w2^T [E][STR] hi/lo bf16 split ----
    {
        const float* w2f = w2 + (size_t)f * (H_DIM * E_DIM);
        #pragma unroll
        for (int i = 0; i < (H_DIM * E_DIM) / 128; i++) {
            int idx = i * 128 + tid;
            int k = idx >> 5;          // hidden index (K)
            int n = idx & 31;          // embed index (N)
            float v = w2f[idx];
            uint32_t hb = __float_as_uint(v) & 0xFFFF0000u;
            w2hi[n * STR + k] = (unsigned short)(hb >> 16);
            float lo = v - __uint_as_float(hb);
            unsigned short ls;
            asm("cvt.rn.bf16.f32 %0, %1;" : "=h"(ls) : "f"(lo));
            w2lo[n * STR + k] = ls;
        }
    }
    __syncthreads();   // only barrier in the kernel; smem read-only afterwards

    // per-thread bias pairs for epilogue (col = nt*8 + 2*tig)
    float2 bb[4];
    #pragma unroll
    for (int nt = 0; nt < 4; nt++)
        bb[nt] = *reinterpret_cast<const float2*>(&b2s[nt * 8 + tig * 2]);

    const int base_row = mgrp * (M_ITERS * M_TILE) + warp * 32;

    // ---- prefetch first tile's x values (rows grp + {0,8,16,24}) ----
    float xv[4];
    #pragma unroll
    for (int j = 0; j < 4; j++)
        xv[j] = x[(size_t)(base_row + grp + j * 8) * F_TOT + f];

    for (int it = 0; it < M_ITERS; it++) {
        const int row0 = base_row + it * M_TILE;

        // prefetch next tile's x
        float xn[4] = {0.f, 0.f, 0.f, 0.f};
        if (it + 1 < M_ITERS) {
            #pragma unroll
            for (int j = 0; j < 4; j++)
                xn[j] = x[(size_t)(row0 + M_TILE + grp + j * 8) * F_TOT + f];
        }

        float c[2][4][4];
        #pragma unroll
        for (int mt = 0; mt < 2; mt++)
            #pragma unroll
            for (int nt = 0; nt < 4; nt++)
                #pragma unroll
                for (int q = 0; q < 4; q++) c[mt][nt][q] = 0.f;

        #pragma unroll
        for (int kt = 0; kt < 8; kt++) {
            const int k0 = kt * 16 + tig * 2;
            const float2 pA = pw[k0];
            const float2 pB = pw[k0 + 1];
            const float2 pC = pw[k0 + 8];
            const float2 pD = pw[k0 + 9];

            // A fragments: h = relu(x*w1+b1), split into bf16 hi (trunc) + lo (RN)
            uint32_t ahi[4][2], alo[4][2];
            #pragma unroll
            for (int j = 0; j < 4; j++) {   // rows grp + j*8  (j = 2*mt + jj)
                float h0 = fmaxf(fmaf(xv[j], pA.x, pA.y), 0.f);
                float h1 = fmaxf(fmaf(xv[j], pB.x, pB.y), 0.f);
                float h2 = fmaxf(fmaf(xv[j], pC.x, pC.y), 0.f);
                float h3 = fmaxf(fmaf(xv[j], pD.x, pD.y), 0.f);
                uint32_t u0 = __float_as_uint(h0), u1 = __float_as_uint(h1);
                uint32_t u2 = __float_as_uint(h2), u3 = __float_as_uint(h3);
                ahi[j][0] = __byte_perm(u0, u1, 0x7632);   // {bf16(h0), bf16(h1)}
                ahi[j][1] = __byte_perm(u2, u3, 0x7632);
                float l0 = h0 - __uint_as_float(u0 & 0xFFFF0000u);
                float l1 = h1 - __uint_as_float(u1 & 0xFFFF0000u);
                float l2 = h2 - __uint_as_float(u2 & 0xFFFF0000u);
                float l3 = h3 - __uint_as_float(u3 & 0xFFFF0000u);
                PACK_BF16X2(alo[j][0], l0, l1);
                PACK_BF16X2(alo[j][1], l2, l3);
            }

            // B fragments from smem (conflict-free), 3-pass hi/lo mma
            #pragma unroll
            for (int nt = 0; nt < 4; nt++) {
                const int n = nt * 8 + grp;
                const int off = n * STR + kt * 16 + tig * 2;   // halves, even
                const uint32_t bh0 = *reinterpret_cast<const uint32_t*>(&w2hi[off]);
                const uint32_t bh1 = *reinterpret_cast<const uint32_t*>(&w2hi[off + 8]);
                const uint32_t bl0 = *reinterpret_cast<const uint32_t*>(&w2lo[off]);
                const uint32_t bl1 = *reinterpret_cast<const uint32_t*>(&w2lo[off + 8]);
                #pragma unroll
                for (int mt = 0; mt < 2; mt++) {
                    MMA16816(c[mt][nt],
                             ahi[2*mt][0], ahi[2*mt+1][0], ahi[2*mt][1], ahi[2*mt+1][1],
                             bh0, bh1);                               // hi*hi
                    MMA16816(c[mt][nt],
                             ahi[2*mt][0], ahi[2*mt+1][0], ahi[2*mt][1], ahi[2*mt+1][1],
                             bl0, bl1);                               // hi*lo
                    MMA16816(c[mt][nt],
                             alo[2*mt][0], alo[2*mt+1][0], alo[2*mt][1], alo[2*mt+1][1],
                             bh0, bh1);                               // lo*hi
                }
            }
        }

        // ---- epilogue: add b2, float2 stores ----
        #pragma unroll
        for (int mt = 0; mt < 2; mt++) {
            const size_t ra = (size_t)(row0 + mt * 16 + grp);
            #pragma unroll
            for (int nt = 0; nt < 4; nt++) {
                const size_t col = (size_t)f * E_DIM + nt * 8 + tig * 2;
                float2 v0, v1;
                v0.x = c[mt][nt][0] + bb[nt].x;
                v0.y = c[mt][nt][1] + bb[nt].y;
                v1.x = c[mt][nt][2] + bb[nt].x;
                v1.y = c[mt][nt][3] + bb[nt].y;
                *reinterpret_cast<float2*>(out + ra * (F_TOT * E_DIM) + col)       = v0;
                *reinterpret_cast<float2*>(out + (ra + 8) * (F_TOT * E_DIM) + col) = v1;
            }
        }

        #pragma unroll
        for (int j = 0; j < 4; j++) xv[j] = xn[j];
    }
}

// ============================================================================
// kernel_launch
// ============================================================================
extern "C" void kernel_launch(void* const* d_in, const int* in_sizes, int n_in,
                              void* d_out, int out_size) {
    const float* x  = (const float*)d_in[0];  // [B, F]
    const float* w1 = (const float*)d_in[1];  // [F, H]
    const float* b1 = (const float*)d_in[2];  // [F, H]
    const float* w2 = (const float*)d_in[3];  // [F, H, E]
    const float* b2 = (const float*)d_in[4];  // [F, E]
    float* out = (float*)d_out;               // [B, F*E]

    dense_feat_emb_kernel<<<GRID, 128>>>(x, w1, b1, w2, b2, out);
}

// round 7
// speedup vs baseline: 1.1675x; 1.1675x over previous
#include <cuda_runtime.h>
#include <cstdint>

// ============================================================================
//   out[b, f*32+e] = sum_h relu(x[b,f]*w1[f,h]+b1[f,h]) * w2[f,h,e] + b2[f,e]
//
// Piecewise-linear reformulation: for fixed f, out is x*Sw(rank)[e]+Sb(rank)[e]
// where rank = #thresholds below x. Precompute sorted thresholds + prefix
// tables, then the main kernel is a binary search + 1 FMA per output element.
// ============================================================================
#define B_TOT 16384
#define F_TOT 128
#define H_DIM 128
#define E_DIM 32

static constexpr int ROWS_PER_CTA = 1024;
static constexpr int MAIN_GRID    = F_TOT * (B_TOT / ROWS_PER_CTA);  // 2048

// ---- device scratch (static allocation is allowed) ----
__device__ float2 g_table[F_TOT][H_DIM + 1][E_DIM];   // 4.2 MB: {Sw, Sb} per rank
__device__ float  g_thresh[F_TOT][H_DIM];             // sorted breakpoints
__device__ float  g_xT[F_TOT][B_TOT];                 // 8 MB: x transposed

// ============================================================================
// Kernel 0: transpose x [B,F] -> xT [F,B] (coalesced main-kernel reads)
// ============================================================================
__global__ void __launch_bounds__(256)
transpose_kernel(const float* __restrict__ x)
{
    __shared__ float tile[32][33];
    const int tx = threadIdx.x, ty = threadIdx.y;       // 32 x 8
    const int b0 = blockIdx.x * 32;                     // 512 blocks
    const int f0 = blockIdx.y * 32;                     // 4 blocks
    #pragma unroll
    for (int i = 0; i < 32; i += 8)
        tile[ty + i][tx] = x[(size_t)(b0 + ty + i) * F_TOT + f0 + tx];
    __syncthreads();
    #pragma unroll
    for (int i = 0; i < 32; i += 8)
        g_xT[f0 + ty + i][b0 + tx] = tile[tx][ty + i];
}

// ============================================================================
// Kernel 1: per-feature breakpoint sort + prefix tables (one CTA per feature)
// ============================================================================
__global__ void __launch_bounds__(128)
precompute_kernel(const float* __restrict__ w1, const float* __restrict__ b1,
                  const float* __restrict__ w2, const float* __restrict__ b2)
{
    const int f = blockIdx.x;
    const int tid = threadIdx.x;   // 128

    __shared__ float tS[H_DIM];
    __shared__ int   hS[H_DIM];
    __shared__ float w1s[H_DIM], b1s[H_DIM];
    __shared__ float w2s[H_DIM][E_DIM];

    const float wv = w1[f * H_DIM + tid];
    const float bv = b1[f * H_DIM + tid];
    w1s[tid] = wv;
    b1s[tid] = bv;
    // breakpoint; w1==0 units are rank-invariant: push to +inf (never crossed)
    tS[tid] = (wv != 0.0f) ? (-bv / wv) : __int_as_float(0x7f800000);
    hS[tid] = tid;

    for (int i = tid; i < H_DIM * E_DIM; i += 128)
        w2s[i >> 5][i & 31] = w2[(size_t)f * (H_DIM * E_DIM) + i];
    __syncthreads();

    // bitonic sort (ascending) on (tS, hS), 128 elements / 128 threads
    for (int k = 2; k <= H_DIM; k <<= 1) {
        for (int j = k >> 1; j > 0; j >>= 1) {
            const int ix = tid ^ j;
            if (ix > tid) {
                const bool up = ((tid & k) == 0);
                const float a = tS[tid], c = tS[ix];
                if ((a > c) == up) {
                    tS[tid] = c; tS[ix] = a;
                    const int hh = hS[tid]; hS[tid] = hS[ix]; hS[ix] = hh;
                }
            }
            __syncthreads();
        }
    }

    g_thresh[f][tid] = tS[tid];

    // prefix tables: threads 0..63 -> (component, e); sequential over ranks
    if (tid < 64) {
        const int  e   = tid & 31;
        const bool isB = tid >= 32;
        float s = 0.0f;
        // base state at x = -inf: all w1<0 active; w1==0 & b1>0 constant-active
        for (int h = 0; h < H_DIM; h++) {
            const float w = w1s[h], b = b1s[h], w2v = w2s[h][e];
            if (w < 0.0f)                       s += (isB ? b : w) * w2v;
            else if (w == 0.0f && b > 0.0f && isB) s += b * w2v;
        }
        if (isB) s += b2[f * E_DIM + e];
        if (isB) g_table[f][0][e].y = s; else g_table[f][0][e].x = s;

        for (int r = 0; r < H_DIM; r++) {
            const int   h = hS[r];
            const float w = w1s[h];
            // crossing upward: w>0 activates (+), w<0 deactivates (-), w==0 no-op
            const float sign = (w > 0.0f) ? 1.0f : ((w < 0.0f) ? -1.0f : 0.0f);
            s += sign * (isB ? b1s[h] : w) * w2s[h][e];
            if (isB) g_table[f][r + 1][e].y = s; else g_table[f][r + 1][e].x = s;
        }
    }
}

// ============================================================================
// Kernel 2: main — binary search + broadcast table read + FMA + coalesced STG
// ============================================================================
__global__ void __launch_bounds__(256)
main_kernel(float* __restrict__ out)
{
    __shared__ float2 tab[(H_DIM + 1) * E_DIM];   // 33 KB
    __shared__ float  th[H_DIM];

    const int tid  = threadIdx.x;
    const int lane = tid & 31;
    const int warp = tid >> 5;
    const int f    = blockIdx.x >> 4;     // 16 row-groups per feature
    const int rg   = blockIdx.x & 15;

    const float2* gt = &g_table[f][0][0];
    for (int i = tid; i < (H_DIM + 1) * E_DIM; i += 256) tab[i] = gt[i];
    if (tid < H_DIM) th[tid] = g_thresh[f][tid];
    __syncthreads();

    const float* xcol = g_xT[f];
    const int row_cta = rg * ROWS_PER_CTA;

    #pragma unroll
    for (int iter = 0; iter < ROWS_PER_CTA / 256; iter++) {   // 4
        const int row0 = row_cta + (iter * 8 + warp) * 32;
        const float xv = xcol[row0 + lane];                   // coalesced

        // rank = #thresholds < xv  (7-step search + tail fixup for rank 128)
        int r = 0;
        #pragma unroll
        for (int s = 64; s; s >>= 1)
            if (xv > th[r + s - 1]) r += s;
        if (r == 127 && xv > th[127]) r = 128;

        float* orow = out + (size_t)row0 * (F_TOT * E_DIM) + f * E_DIM + lane;
        #pragma unroll
        for (int j = 0; j < 32; j++) {
            const int   rj = __shfl_sync(0xffffffffu, r,  j);
            const float xj = __shfl_sync(0xffffffffu, xv, j);
            const float2 v = tab[rj * E_DIM + lane];          // broadcast row, conflict-free
            orow[(size_t)j * (F_TOT * E_DIM)] = fmaf(xj, v.x, v.y);
        }
    }
}

// ============================================================================
// kernel_launch
// ============================================================================
extern "C" void kernel_launch(void* const* d_in, const int* in_sizes, int n_in,
                              void* d_out, int out_size) {
    const float* x  = (const float*)d_in[0];  // [B, F]
    const float* w1 = (const float*)d_in[1];  // [F, H]
    const float* b1 = (const float*)d_in[2];  // [F, H]
    const float* w2 = (const float*)d_in[3];  // [F, H, E]
    const float* b2 = (const float*)d_in[4];  // [F, E]
    float* out = (float*)d_out;               // [B, F*E]

    transpose_kernel<<<dim3(B_TOT / 32, F_TOT / 32), dim3(32, 8)>>>(x);
    precompute_kernel<<<F_TOT, 128>>>(w1, b1, w2, b2);
    main_kernel<<<MAIN_GRID, 256>>>(out);
}

// round 8
// speedup vs baseline: 1.5538x; 1.3308x over previous
#include <cuda_runtime.h>
#include <cstdint>

// ============================================================================
//   out[b, f*32+e] = sum_h relu(x[b,f]*w1[f,h]+b1[f,h]) * w2[f,h,e] + b2[f,e]
//
// Piecewise-linear reformulation: for fixed f, out = x*Sw(rank)[e]+Sb(rank)[e],
// rank = #breakpoints below x. Precompute sorted breakpoints + prefix tables;
// main kernel = binary search + table FMA, vectorized 4 rows / warp-step.
// ============================================================================
#define B_TOT 16384
#define F_TOT 128
#define H_DIM 128
#define E_DIM 32

static constexpr int ROWS_PER_CTA = 1024;
static constexpr int MAIN_GRID    = F_TOT * (B_TOT / ROWS_PER_CTA);  // 2048
static constexpr int TSTR         = 34;   // tab row stride in float2 (16B-aligned, conflict-light)

// ---- device scratch (static allocation allowed) ----
__device__ float2 g_table[F_TOT][H_DIM + 1][E_DIM];   // {Sw, Sb} per rank
__device__ float  g_thresh[F_TOT][H_DIM];             // sorted breakpoints
__device__ float  g_xT[F_TOT][B_TOT];                 // x transposed

// ============================================================================
// Kernel 0: transpose x [B,F] -> xT [F,B]
// ============================================================================
__global__ void __launch_bounds__(256)
transpose_kernel(const float* __restrict__ x)
{
    __shared__ float tile[32][33];
    const int tx = threadIdx.x, ty = threadIdx.y;       // 32 x 8
    const int b0 = blockIdx.x * 32;
    const int f0 = blockIdx.y * 32;
    #pragma unroll
    for (int i = 0; i < 32; i += 8)
        tile[ty + i][tx] = x[(size_t)(b0 + ty + i) * F_TOT + f0 + tx];
    __syncthreads();
    #pragma unroll
    for (int i = 0; i < 32; i += 8)
        g_xT[f0 + ty + i][b0 + tx] = tile[tx][ty + i];
}

// ============================================================================
// Kernel 1: per-feature breakpoint sort + prefix tables (one CTA per feature)
// ============================================================================
__global__ void __launch_bounds__(128)
precompute_kernel(const float* __restrict__ w1, const float* __restrict__ b1,
                  const float* __restrict__ w2, const float* __restrict__ b2)
{
    const int f = blockIdx.x;
    const int tid = threadIdx.x;   // 128

    __shared__ float tS[H_DIM];
    __shared__ int   hS[H_DIM];
    __shared__ float w1s[H_DIM], b1s[H_DIM];
    __shared__ float w2s[H_DIM][E_DIM];

    const float wv = w1[f * H_DIM + tid];
    const float bv = b1[f * H_DIM + tid];
    w1s[tid] = wv;
    b1s[tid] = bv;
    tS[tid] = (wv != 0.0f) ? (-bv / wv) : __int_as_float(0x7f800000);
    hS[tid] = tid;

    for (int i = tid; i < H_DIM * E_DIM; i += 128)
        w2s[i >> 5][i & 31] = w2[(size_t)f * (H_DIM * E_DIM) + i];
    __syncthreads();

    // bitonic sort (ascending) on (tS, hS)
    for (int k = 2; k <= H_DIM; k <<= 1) {
        for (int j = k >> 1; j > 0; j >>= 1) {
            const int ix = tid ^ j;
            if (ix > tid) {
                const bool up = ((tid & k) == 0);
                const float a = tS[tid], c = tS[ix];
                if ((a > c) == up) {
                    tS[tid] = c; tS[ix] = a;
                    const int hh = hS[tid]; hS[tid] = hS[ix]; hS[ix] = hh;
                }
            }
            __syncthreads();
        }
    }

    g_thresh[f][tid] = tS[tid];

    // prefix tables: threads 0..63 -> (component, e); sequential over ranks
    if (tid < 64) {
        const int  e   = tid & 31;
        const bool isB = tid >= 32;
        float s = 0.0f;
        for (int h = 0; h < H_DIM; h++) {
            const float w = w1s[h], b = b1s[h], w2v = w2s[h][e];
            if (w < 0.0f)                          s += (isB ? b : w) * w2v;
            else if (w == 0.0f && b > 0.0f && isB) s += b * w2v;
        }
        if (isB) s += b2[f * E_DIM + e];
        if (isB) g_table[f][0][e].y = s; else g_table[f][0][e].x = s;

        for (int r = 0; r < H_DIM; r++) {
            const int   h = hS[r];
            const float w = w1s[h];
            const float sign = (w > 0.0f) ? 1.0f : ((w < 0.0f) ? -1.0f : 0.0f);
            s += sign * (isB ? b1s[h] : w) * w2s[h][e];
            if (isB) g_table[f][r + 1][e].y = s; else g_table[f][r + 1][e].x = s;
        }
    }
}

// ============================================================================
// Kernel 2: main — search once per row; emit 4 rows per warp-step via
// LDS.128 table reads + STG.128 stores.
// ============================================================================
__global__ void __launch_bounds__(256)
main_kernel(float* __restrict__ out)
{
    __shared__ float2 tab[(H_DIM + 1) * TSTR];   // padded rows, ~35 KB
    __shared__ float  th[H_DIM];

    const int tid  = threadIdx.x;
    const int lane = tid & 31;
    const int warp = tid >> 5;
    const int f    = blockIdx.x >> 4;     // 16 row-groups per feature
    const int rg   = blockIdx.x & 15;

    const float2* gt = &g_table[f][0][0];
    for (int i = tid; i < (H_DIM + 1) * E_DIM; i += 256)
        tab[(i >> 5) * TSTR + (i & 31)] = gt[i];
    if (tid < H_DIM) th[tid] = g_thresh[f][tid];
    __syncthreads();

    const float* xcol = g_xT[f];
    const int row_cta = rg * ROWS_PER_CTA;

    const int rq = lane >> 3;   // row within quad
    const int e4 = lane & 7;    // float4 slot within the 32-wide embed row

    for (int iter = 0; iter < ROWS_PER_CTA / 256; iter++) {   // 4
        const int row0 = row_cta + (iter * 8 + warp) * 32;
        const float xv = xcol[row0 + lane];                   // coalesced

        // rank = #thresholds < xv
        int r = 0;
        #pragma unroll
        for (int s = 64; s; s >>= 1)
            if (xv > th[r + s - 1]) r += s;
        if (r == 127 && xv > th[127]) r = 128;

        float* obase = out + (size_t)(row0 + rq) * (F_TOT * E_DIM)
                           + f * E_DIM + e4 * 4;

        #pragma unroll
        for (int j = 0; j < 8; j++) {                         // 4 rows per step
            const int   src = j * 4 + rq;
            const int   rj  = __shfl_sync(0xffffffffu, r,  src);
            const float xj  = __shfl_sync(0xffffffffu, xv, src);
            const float2* trow = &tab[rj * TSTR + e4 * 4];
            const float4 p0 = *reinterpret_cast<const float4*>(trow);      // e4*4+0,1
            const float4 p1 = *reinterpret_cast<const float4*>(trow + 2);  // e4*4+2,3
            float4 o;
            o.x = fmaf(xj, p0.x, p0.y);
            o.y = fmaf(xj, p0.z, p0.w);
            o.z = fmaf(xj, p1.x, p1.y);
            o.w = fmaf(xj, p1.z, p1.w);
            *reinterpret_cast<float4*>(obase + (size_t)(j * 4) * (F_TOT * E_DIM)) = o;
        }
    }
}

// ============================================================================
// kernel_launch
// ============================================================================
extern "C" void kernel_launch(void* const* d_in, const int* in_sizes, int n_in,
                              void* d_out, int out_size) {
    const float* x  = (const float*)d_in[0];  // [B, F]
    const float* w1 = (const float*)d_in[1];  // [F, H]
    const float* b1 = (const float*)d_in[2];  // [F, H]
    const float* w2 = (const float*)d_in[3];  // [F, H, E]
    const float* b2 = (const float*)d_in[4];  // [F, E]
    float* out = (float*)d_out;               // [B, F*E]

    transpose_kernel<<<dim3(B_TOT / 32, F_TOT / 32), dim3(32, 8)>>>(x);
    precompute_kernel<<<F_TOT, 128>>>(w1, b1, w2, b2);
    main_kernel<<<MAIN_GRID, 256>>>(out);
}

// round 9
// speedup vs baseline: 1.8760x; 1.2074x over previous
#include <cuda_runtime.h>
#include <cstdint>

// ============================================================================
//   out[b, f*32+e] = sum_h relu(x[b,f]*w1[f,h]+b1[f,h]) * w2[f,h,e] + b2[f,e]
//
// Piecewise-linear reformulation: for fixed f, out = x*Sw(rank)[e]+Sb(rank)[e],
// rank = #breakpoints below x. Precompute sorted breakpoints + prefix tables;
// main kernel = binary search + table FMA, 4 rows per warp-step via LDS.128 /
// STG.128, (x,rank) distributed through per-warp smem staging.
// ============================================================================
#define B_TOT 16384
#define F_TOT 128
#define H_DIM 128
#define E_DIM 32

static constexpr int ROWS_PER_CTA = 1024;
static constexpr int MAIN_GRID    = F_TOT * (B_TOT / ROWS_PER_CTA);  // 2048
static constexpr int TSTR         = 34;   // tab row stride in float2

// ---- device scratch (static allocation allowed) ----
__device__ float2 g_table[F_TOT][H_DIM + 1][E_DIM];   // {Sw, Sb} per rank
__device__ float  g_thresh[F_TOT][H_DIM];             // sorted breakpoints
__device__ float  g_xT[F_TOT][B_TOT];                 // x transposed

// ============================================================================
// Kernel 0: transpose x [B,F] -> xT [F,B]
// ============================================================================
__global__ void __launch_bounds__(256)
transpose_kernel(const float* __restrict__ x)
{
    __shared__ float tile[32][33];
    const int tx = threadIdx.x, ty = threadIdx.y;       // 32 x 8
    const int b0 = blockIdx.x * 32;
    const int f0 = blockIdx.y * 32;
    #pragma unroll
    for (int i = 0; i < 32; i += 8)
        tile[ty + i][tx] = x[(size_t)(b0 + ty + i) * F_TOT + f0 + tx];
    __syncthreads();
    #pragma unroll
    for (int i = 0; i < 32; i += 8)
        g_xT[f0 + ty + i][b0 + tx] = tile[tx][ty + i];
}

// ============================================================================
// Kernel 1: per-feature breakpoint sort + prefix tables (one CTA per feature)
// ============================================================================
__global__ void __launch_bounds__(128)
precompute_kernel(const float* __restrict__ w1, const float* __restrict__ b1,
                  const float* __restrict__ w2, const float* __restrict__ b2)
{
    const int f = blockIdx.x;
    const int tid = threadIdx.x;   // 128

    __shared__ float tS[H_DIM];
    __shared__ int   hS[H_DIM];
    __shared__ float w1s[H_DIM], b1s[H_DIM];
    __shared__ float w2s[H_DIM][E_DIM];

    const float wv = w1[f * H_DIM + tid];
    const float bv = b1[f * H_DIM + tid];
    w1s[tid] = wv;
    b1s[tid] = bv;
    tS[tid] = (wv != 0.0f) ? (-bv / wv) : __int_as_float(0x7f800000);
    hS[tid] = tid;

    for (int i = tid; i < H_DIM * E_DIM; i += 128)
        w2s[i >> 5][i & 31] = w2[(size_t)f * (H_DIM * E_DIM) + i];
    __syncthreads();

    // bitonic sort (ascending) on (tS, hS)
    for (int k = 2; k <= H_DIM; k <<= 1) {
        for (int j = k >> 1; j > 0; j >>= 1) {
            const int ix = tid ^ j;
            if (ix > tid) {
                const bool up = ((tid & k) == 0);
                const float a = tS[tid], c = tS[ix];
                if ((a > c) == up) {
                    tS[tid] = c; tS[ix] = a;
                    const int hh = hS[tid]; hS[tid] = hS[ix]; hS[ix] = hh;
                }
            }
            __syncthreads();
        }
    }

    g_thresh[f][tid] = tS[tid];

    // prefix tables: threads 0..63 -> (component, e); sequential over ranks
    if (tid < 64) {
        const int  e   = tid & 31;
        const bool isB = tid >= 32;
        float s = 0.0f;
        for (int h = 0; h < H_DIM; h++) {
            const float w = w1s[h], b = b1s[h], w2v = w2s[h][e];
            if (w < 0.0f)                          s += (isB ? b : w) * w2v;
            else if (w == 0.0f && b > 0.0f && isB) s += b * w2v;
        }
        if (isB) s += b2[f * E_DIM + e];
        if (isB) g_table[f][0][e].y = s; else g_table[f][0][e].x = s;

        for (int r = 0; r < H_DIM; r++) {
            const int   h = hS[r];
            const float w = w1s[h];
            const float sign = (w > 0.0f) ? 1.0f : ((w < 0.0f) ? -1.0f : 0.0f);
            s += sign * (isB ? b1s[h] : w) * w2s[h][e];
            if (isB) g_table[f][r + 1][e].y = s; else g_table[f][r + 1][e].x = s;
        }
    }
}

// ============================================================================
// Kernel 2: main
// ============================================================================
__global__ void __launch_bounds__(256)
main_kernel(float* __restrict__ out)
{
    __shared__ float2 tab[(H_DIM + 1) * TSTR];   // ~35 KB padded
    __shared__ float  th[H_DIM];
    __shared__ float2 stage[8][32];              // per-warp (x, rank) staging

    const int tid  = threadIdx.x;
    const int lane = tid & 31;
    const int warp = tid >> 5;
    const int f    = blockIdx.x >> 4;     // 16 row-groups per feature
    const int rg   = blockIdx.x & 15;

    const float2* gt = &g_table[f][0][0];
    for (int i = tid; i < (H_DIM + 1) * E_DIM; i += 256)
        tab[(i >> 5) * TSTR + (i & 31)] = gt[i];
    if (tid < H_DIM) th[tid] = g_thresh[f][tid];
    __syncthreads();

    const float* xcol = g_xT[f];
    const int row_cta = rg * ROWS_PER_CTA;

    const int rq = lane >> 3;   // row within quad
    const int e4 = lane & 7;    // float4 slot within the 32-wide embed row

    float2* const my_stage = &stage[warp][0];

    for (int iter = 0; iter < ROWS_PER_CTA / 256; iter++) {   // 4
        const int row0 = row_cta + (iter * 8 + warp) * 32;
        const float xv = __ldcs(&xcol[row0 + lane]);          // read-once stream

        // rank = #thresholds < xv
        int r = 0;
        #pragma unroll
        for (int s = 64; s; s >>= 1)
            if (xv > th[r + s - 1]) r += s;
        if (r == 127 && xv > th[127]) r = 128;

        __syncwarp();                                    // prev iter reads done
        my_stage[lane] = make_float2(xv, __int_as_float(r));
        __syncwarp();                                    // publish

        float* obase = out + (size_t)(row0 + rq) * (F_TOT * E_DIM)
                           + f * E_DIM + e4 * 4;

        #pragma unroll
        for (int j = 0; j < 8; j++) {                    // 4 rows per step
            const float2 pr = my_stage[j * 4 + rq];      // broadcast LDS.64
            const float xj  = pr.x;
            const int   rj  = __float_as_int(pr.y);
            const float2* trow = &tab[rj * TSTR + e4 * 4];
            const float4 p0 = *reinterpret_cast<const float4*>(trow);
            const float4 p1 = *reinterpret_cast<const float4*>(trow + 2);
            float4 o;
            o.x = fmaf(xj, p0.x, p0.y);
            o.y = fmaf(xj, p0.z, p0.w);
            o.z = fmaf(xj, p1.x, p1.y);
            o.w = fmaf(xj, p1.z, p1.w);
            __stcs(reinterpret_cast<float4*>(
                       obase + (size_t)(j * 4) * (F_TOT * E_DIM)), o);
        }
    }
}

// ============================================================================
// kernel_launch
// ============================================================================
extern "C" void kernel_launch(void* const* d_in, const int* in_sizes, int n_in,
                              void* d_out, int out_size) {
    const float* x  = (const float*)d_in[0];  // [B, F]
    const float* w1 = (const float*)d_in[1];  // [F, H]
    const float* b1 = (const float*)d_in[2];  // [F, H]
    const float* w2 = (const float*)d_in[3];  // [F, H, E]
    const float* b2 = (const float*)d_in[4];  // [F, E]
    float* out = (float*)d_out;               // [B, F*E]

    transpose_kernel<<<dim3(B_TOT / 32, F_TOT / 32), dim3(32, 8)>>>(x);
    precompute_kernel<<<F_TOT, 128>>>(w1, b1, w2, b2);
    main_kernel<<<MAIN_GRID, 256>>>(out);
}